// round 6
// baseline (speedup 1.0000x reference)
#include <cuda_runtime.h>
#include <cuda_fp16.h>
#include <cstdint>

#define N_NODES 8192
#define IN_F 256
#define OUT_F 64
#define ALPHA 0.3f
#define JSPLIT 8
#define ROWTILE 128
#define KCH 64            // columns (K) per chunk
#define NCHUNK 16         // (8192/JSPLIT)/KCH
#define NWHBLK 512        // wh_kernel blocks (16 rows each)
#define PROW 72           // padded SMEM row stride in halves (144 B)

// dynamic SMEM layout (bytes)
#define OFF_A0   0
#define OFF_A1   32768
#define OFF_P    65536
#define OFF_B0   83968
#define OFF_B1   93184
#define OFF_DST  102400
#define SMEM_DYN 106496

// ---------------- device scratch (no allocations allowed) ----------------
__device__ __half g_WhT[OUT_F * N_NODES];            // Wh^T fp16 [64][8192], 1 MB
__device__ float g_src[N_NODES];
__device__ float g_dst[N_NODES];
__device__ float g_blockmax[NWHBLK];
__device__ float g_pacc[JSPLIT][N_NODES][OUT_F];     // 16 MB fp32 partials
__device__ float g_pden[JSPLIT][N_NODES];

__device__ __forceinline__ uint32_t smem_u32(const void* p) {
    uint32_t a;
    asm("{ .reg .u64 t; cvta.to.shared.u64 t, %1; cvt.u32.u64 %0, t; }" : "=r"(a) : "l"(p));
    return a;
}
__device__ __forceinline__ void cp16(uint32_t s, const void* g) {
    asm volatile("cp.async.cg.shared.global [%0], [%1], 16;" :: "r"(s), "l"(g));
}
#define CP_COMMIT()  asm volatile("cp.async.commit_group;" ::: "memory")
#define CP_WAIT1()   asm volatile("cp.async.wait_group 1;" ::: "memory")
__device__ __forceinline__ void ldmatrix_x4(uint32_t& r0, uint32_t& r1, uint32_t& r2,
                                            uint32_t& r3, uint32_t addr) {
    asm volatile("ldmatrix.sync.aligned.m8n8.x4.shared.b16 {%0,%1,%2,%3}, [%4];"
                 : "=r"(r0), "=r"(r1), "=r"(r2), "=r"(r3) : "r"(addr));
}
__device__ __forceinline__ void mma_16816(float* c, uint32_t a0, uint32_t a1,
                                          uint32_t a2, uint32_t a3,
                                          uint32_t b0, uint32_t b1) {
    asm volatile(
        "mma.sync.aligned.m16n8k16.row.col.f32.f16.f16.f32 "
        "{%0,%1,%2,%3}, {%4,%5,%6,%7}, {%8,%9}, {%0,%1,%2,%3};"
        : "+f"(c[0]), "+f"(c[1]), "+f"(c[2]), "+f"(c[3])
        : "r"(a0), "r"(a1), "r"(a2), "r"(a3), "r"(b0), "r"(b1));
}

// ---------------------------------------------------------------------------
// Kernel 1: Wh = h @ W; WhT fp16 [64][8192], src/dst fp32, per-block dst max.
// Grid 512 (16 rows/block), 256 threads: thread = 1 row x 4 feats.
// ---------------------------------------------------------------------------
__global__ __launch_bounds__(256) void wh_kernel(const float* __restrict__ h,
                                                 const float* __restrict__ W,
                                                 const float* __restrict__ a) {
    __shared__ float sh[16][64];
    __shared__ float sW[64][64];
    __shared__ __half sWh[64][16];
    __shared__ float dtile[16];
    const int tid = threadIdx.x;
    const int tx = tid & 15;        // feat group (4 feats)
    const int ty = tid >> 4;        // row 0..15
    const int I0 = blockIdx.x * 16;

    float acc[4] = {};

    for (int kt = 0; kt < 4; kt++) {
        __syncthreads();
        {   // h tile 16x64: 256 float4 slots, 1 per thread
            const int r = tid >> 4, c = (tid & 15) << 2;
            *reinterpret_cast<float4*>(&sh[r][c]) = *reinterpret_cast<const float4*>(
                &h[(size_t)(I0 + r) * IN_F + kt * 64 + c]);
        }
#pragma unroll
        for (int it = 0; it < 4; it++) {  // W tile 64x64: 1024 float4 slots
            const int s = tid + it * 256;
            const int r = s >> 4, c = (s & 15) << 2;
            *reinterpret_cast<float4*>(&sW[r][c]) = *reinterpret_cast<const float4*>(
                &W[(size_t)(kt * 64 + r) * OUT_F + c]);
        }
        __syncthreads();
#pragma unroll 8
        for (int k = 0; k < 64; k++) {
            const float4 wv = *reinterpret_cast<const float4*>(&sW[k][tx << 2]);
            const float hh = sh[ty][k];
            acc[0] += hh * wv.x; acc[1] += hh * wv.y;
            acc[2] += hh * wv.z; acc[3] += hh * wv.w;
        }
    }

    // stage fp16 transpose in SMEM, then coalesced 16B writes to WhT
    __syncthreads();
#pragma unroll
    for (int ff = 0; ff < 4; ff++) sWh[tx * 4 + ff][ty] = __float2half(acc[ff]);

    const float4 as = *reinterpret_cast<const float4*>(&a[tx << 2]);
    const float4 ad = *reinterpret_cast<const float4*>(&a[OUT_F + (tx << 2)]);
    float sp = acc[0] * as.x + acc[1] * as.y + acc[2] * as.z + acc[3] * as.w;
    float dp = acc[0] * ad.x + acc[1] * ad.y + acc[2] * ad.z + acc[3] * ad.w;
#pragma unroll
    for (int o = 1; o < 16; o <<= 1) {
        sp += __shfl_xor_sync(0xffffffffu, sp, o);
        dp += __shfl_xor_sync(0xffffffffu, dp, o);
    }
    if (tx == 0) {
        g_src[I0 + ty] = sp;
        g_dst[I0 + ty] = dp;
        dtile[ty] = dp;
    }
    __syncthreads();
    if (tid < 128) {  // 64 feats x 2 halves-of-16
        const int f = tid >> 1, part = tid & 1;
        *reinterpret_cast<uint4*>(&g_WhT[(size_t)f * N_NODES + I0 + part * 8]) =
            *reinterpret_cast<const uint4*>(&sWh[f][part * 8]);
    }
    if (tid == 0) {
        float mm = dtile[0];
        for (int q = 1; q < 16; q++) mm = fmaxf(mm, dtile[q]);
        g_blockmax[blockIdx.x] = mm;
    }
}

// ---------------------------------------------------------------------------
// Kernel 2: masked dense attention GEMM; cp.async double-buffered adj/B.
// Block = 128 rows x 1024 cols (grid 512), 256 threads.
// Pipeline per chunk: issue cp.async for ch+1, wait group ch, P-gen
// (p = adj * exp(lrelu(src+dst)-proxy)) from SMEM adj, HMMA into registers.
// ---------------------------------------------------------------------------
__global__ __launch_bounds__(256, 2) void attn_kernel(const float* __restrict__ adj) {
    extern __shared__ char dsm[];
    __shared__ float sBm[8];
    __shared__ float sDmax;

    const uint32_t base = smem_u32(dsm);
    const uint32_t aSm[2] = {base + OFF_A0, base + OFF_A1};
    const uint32_t bSm[2] = {base + OFF_B0, base + OFF_B1};
    float* const sA[2] = {reinterpret_cast<float*>(dsm + OFF_A0),
                          reinterpret_cast<float*>(dsm + OFF_A1)};
    __half* const sP = reinterpret_cast<__half*>(dsm + OFF_P);
    float* const sDst = reinterpret_cast<float*>(dsm + OFF_DST);

    const int tid = threadIdx.x;
    const int w = tid >> 5, lane = tid & 31;
    const int q = tid & 15, r0 = tid >> 4;    // P-gen: cols q*4.., rows r0+16m
    const int rt = blockIdx.x >> 3, js = blockIdx.x & 7;
    const int I0 = rt * ROWTILE;
    const int jbase = js * (N_NODES / JSPLIT);

    // ---- prime chunk 0 (adj + B) ----
    {
#pragma unroll
        for (int m8 = 0; m8 < 8; m8++)
            cp16(aSm[0] + (uint32_t)(((r0 + 16 * m8) * KCH + q * 4) * 4),
                 &adj[(size_t)(I0 + r0 + 16 * m8) * N_NODES + jbase + q * 4]);
#pragma unroll
        for (int it = 0; it < 2; it++) {
            const int idx = tid + it * 256;
            const int f = idx >> 3, u = idx & 7;
            cp16(bSm[0] + (uint32_t)((f * PROW + u * 8) * 2),
                 &g_WhT[(size_t)f * N_NODES + jbase + u * 8]);
        }
        CP_COMMIT();
    }

    // ---- dst slice + dmax ----
    *reinterpret_cast<float4*>(&sDst[tid * 4]) =
        __ldg(reinterpret_cast<const float4*>(&g_dst[jbase]) + tid);
    {
        float m = fmaxf(g_blockmax[tid], g_blockmax[tid + 256]);
#pragma unroll
        for (int o = 16; o; o >>= 1) m = fmaxf(m, __shfl_xor_sync(0xffffffffu, m, o));
        if (lane == 0) sBm[w] = m;
    }
    __syncthreads();
    if (tid == 0) {
        float mm = sBm[0];
        for (int s = 1; s < 8; s++) mm = fmaxf(mm, sBm[s]);
        sDmax = mm;
    }
    __syncthreads();
    const float dmax = sDmax;

    float srcv[8], proxy[8], den[8];
#pragma unroll
    for (int m8 = 0; m8 < 8; m8++) {
        const float s = __ldg(&g_src[I0 + r0 + 16 * m8]);
        srcv[m8] = s;
        const float e = s + dmax;
        proxy[m8] = e > 0.f ? e : ALPHA * e;
        den[m8] = 0.f;
    }

    // ldmatrix addresses
    const uint32_t pbase = base + OFF_P;
    const uint32_t aAddr = pbase + ((16 * w + (lane & 15)) * PROW + (lane >> 4) * 8) * 2;
    const uint32_t bRow = (lane & 7) + ((lane & 16) ? 8 : 0);
    const uint32_t bKoff = (lane & 8) ? 8 : 0;
    const uint32_t bFragOff = (bRow * PROW + bKoff) * 2;

    float acc[8][4] = {};

    for (int ch = 0; ch < NCHUNK; ch++) {
        const int buf = ch & 1;

        // issue ch+1 (into buf^1), always commit (empty group keeps wait depth)
        if (ch + 1 < NCHUNK) {
            const int jn = jbase + (ch + 1) * KCH;
#pragma unroll
            for (int m8 = 0; m8 < 8; m8++)
                cp16(aSm[buf ^ 1] + (uint32_t)(((r0 + 16 * m8) * KCH + q * 4) * 4),
                     &adj[(size_t)(I0 + r0 + 16 * m8) * N_NODES + jn + q * 4]);
#pragma unroll
            for (int it = 0; it < 2; it++) {
                const int idx = tid + it * 256;
                const int f = idx >> 3, u = idx & 7;
                cp16(bSm[buf ^ 1] + (uint32_t)((f * PROW + u * 8) * 2),
                     &g_WhT[(size_t)f * N_NODES + jn + u * 8]);
            }
        }
        CP_COMMIT();
        CP_WAIT1();        // chunk ch's group complete
        __syncthreads();   // visible to all; prior phase fully done

        // ---- P generation from SMEM adj ----
        const float4 dv = *reinterpret_cast<const float4*>(&sDst[ch * KCH + q * 4]);
#pragma unroll
        for (int m8 = 0; m8 < 8; m8++) {
            const float4 av = *reinterpret_cast<const float4*>(
                &sA[buf][(r0 + 16 * m8) * KCH + q * 4]);
            const float sv = srcv[m8], px = proxy[m8];
            float e0 = sv + dv.x, e1 = sv + dv.y, e2 = sv + dv.z, e3 = sv + dv.w;
            e0 = fmaxf(e0, ALPHA * e0);  e1 = fmaxf(e1, ALPHA * e1);
            e2 = fmaxf(e2, ALPHA * e2);  e3 = fmaxf(e3, ALPHA * e3);
            const float p0 = av.x * __expf(e0 - px);
            const float p1 = av.y * __expf(e1 - px);
            const float p2 = av.z * __expf(e2 - px);
            const float p3 = av.w * __expf(e3 - px);
            den[m8] += (p0 + p1) + (p2 + p3);
            uint2 pk;
            const __half2 h01 = __floats2half2_rn(p0, p1);
            const __half2 h23 = __floats2half2_rn(p2, p3);
            pk.x = *reinterpret_cast<const uint32_t*>(&h01);
            pk.y = *reinterpret_cast<const uint32_t*>(&h23);
            *reinterpret_cast<uint2*>(&sP[(r0 + 16 * m8) * PROW + q * 4]) = pk;
        }
        __syncthreads();   // P ready (B[buf] already resident)

        // ---- MMA: warp w does D[16w..16w+15][0..63] += P*B^T ----
        const uint32_t bAddr0 = bSm[buf] + bFragOff;
#pragma unroll
        for (int kk = 0; kk < 4; kk++) {
            uint32_t a0, a1, a2, a3;
            ldmatrix_x4(a0, a1, a2, a3, aAddr + kk * 32);
#pragma unroll
            for (int np = 0; np < 4; np++) {
                uint32_t b0, b1, b2, b3;
                ldmatrix_x4(b0, b1, b2, b3, bAddr0 + (np * 16 * PROW + kk * 16) * 2);
                mma_16816(acc[2 * np],     a0, a1, a2, a3, b0, b1);
                mma_16816(acc[2 * np + 1], a0, a1, a2, a3, b2, b3);
            }
        }
        __syncthreads();   // end of chunk: P/adj buffers reusable
    }

    // ---- den: reduce over q (16-lane groups) ----
#pragma unroll
    for (int m8 = 0; m8 < 8; m8++) {
        float d = den[m8];
#pragma unroll
        for (int o = 1; o < 16; o <<= 1) d += __shfl_xor_sync(0xffffffffu, d, o);
        if (q == 0) g_pden[js][I0 + r0 + 16 * m8] = d;
    }

    // ---- D epilogue (fragment layout) ----
    {
        const int g = lane >> 2, t = lane & 3;
        const int row0 = I0 + 16 * w + g;
#pragma unroll
        for (int nt = 0; nt < 8; nt++) {
            const int col = nt * 8 + t * 2;
            *reinterpret_cast<float2*>(&g_pacc[js][row0][col]) =
                make_float2(acc[nt][0], acc[nt][1]);
            *reinterpret_cast<float2*>(&g_pacc[js][row0 + 8][col]) =
                make_float2(acc[nt][2], acc[nt][3]);
        }
    }
}

// ---------------------------------------------------------------------------
// Kernel 3: combine J-split partials, normalize, ELU.
// ---------------------------------------------------------------------------
__global__ __launch_bounds__(256) void combine_kernel(float* __restrict__ out) {
    const int idx = blockIdx.x * 256 + threadIdx.x;  // over 8192*64
    const int i = idx >> 6, f = idx & 63;
    float sum = 0.f, d = 0.f;
#pragma unroll
    for (int js = 0; js < JSPLIT; js++) {
        sum += g_pacc[js][i][f];
        d   += g_pden[js][i];
    }
    const float v = sum / d;
    out[idx] = v > 0.f ? v : expm1f(v);
}

// ---------------------------------------------------------------------------
// inputs: h [8192,256] f32, adj [8192,8192] f32, W [256,64] f32, a [128,1] f32
// output: [8192,64] f32
// ---------------------------------------------------------------------------
extern "C" void kernel_launch(void* const* d_in, const int* in_sizes, int n_in,
                              void* d_out, int out_size) {
    const float* h   = (const float*)d_in[0];
    const float* adj = (const float*)d_in[1];
    const float* W   = (const float*)d_in[2];
    const float* a   = (const float*)d_in[3];
    float* out = (float*)d_out;

    static int attr_done = 0;
    if (!attr_done) {
        cudaFuncSetAttribute(attn_kernel, cudaFuncAttributeMaxDynamicSharedMemorySize,
                             SMEM_DYN);
        attr_done = 1;
    }

    wh_kernel<<<NWHBLK, 256>>>(h, W, a);
    attn_kernel<<<(N_NODES / ROWTILE) * JSPLIT, 256, SMEM_DYN>>>(adj);
    combine_kernel<<<(N_NODES * OUT_F) / 256, 256>>>(out);
}